// round 1
// baseline (speedup 1.0000x reference)
#include <cuda_runtime.h>
#include <cuda_bf16.h>
#include <math.h>

// Problem constants
#define N_ 30000
#define D_ 128
#define E_ 240000
#define E2_ (E_ + N_)          // edges + self loops = 270000
#define L_ 6
#define NEG_SLOPE 0.2f
#define EPS_ 1e-5f

// -------------------- device scratch (static, no allocs) --------------------
__device__ float g_h[N_ * D_];      // initial embeddings
__device__ float g_xg[N_ * D_];     // layer activation (pre-LN)
__device__ float g_xl[N_ * D_];     // source transform
__device__ float g_xr[N_ * D_];     // target transform

__device__ int    g_deg[N_];
__device__ int    g_cursor[N_];
__device__ int    g_rowptr[N_ + 1];
__device__ int    g_srcs[E2_];

__device__ double g_lnred[12];      // [layer][2] sum, sumsq (layers 0..4 used)
__device__ float  g_bnsum[D_];
__device__ float  g_bnsq[D_];

// -------------------- helpers --------------------
__device__ __forceinline__ float leaky(float v) {
    return v > 0.f ? v : NEG_SLOPE * v;
}

// -------------------- zero counters --------------------
__global__ void zero_kernel() {
    int i = blockIdx.x * blockDim.x + threadIdx.x;
    if (i < N_) { g_deg[i] = 0; g_cursor[i] = 0; }
    if (i < 12) g_lnred[i] = 0.0;
    if (i < D_) { g_bnsum[i] = 0.f; g_bnsq[i] = 0.f; }
}

// -------------------- h = emb[x] --------------------
__global__ void gather_kernel(const int* __restrict__ x,
                              const float* __restrict__ emb) {
    int i = blockIdx.x * blockDim.x + threadIdx.x;   // over N_*32 float4s
    if (i >= N_ * 32) return;
    int n = i >> 5, c4 = i & 31;
    ((float4*)g_h)[i] = ((const float4*)(emb + (size_t)x[n] * D_))[c4];
}

// -------------------- CSR build --------------------
__global__ void hist_kernel(const int* __restrict__ ei) {
    int e = blockIdx.x * blockDim.x + threadIdx.x;
    if (e >= E2_) return;
    int d = (e < E_) ? ei[E_ + e] : (e - E_);
    atomicAdd(&g_deg[d], 1);
}

__global__ void scan_kernel() {
    __shared__ int sh[1024];
    const int t = threadIdx.x;
    const int CH = 30;                     // 1024*30 = 30720 >= 30001
    int base = t * CH;
    int s = 0;
    for (int j = 0; j < CH; j++) {
        int idx = base + j;
        if (idx < N_) s += g_deg[idx];
    }
    sh[t] = s;
    __syncthreads();
    for (int off = 1; off < 1024; off <<= 1) {
        int v = (t >= off) ? sh[t - off] : 0;
        __syncthreads();
        sh[t] += v;
        __syncthreads();
    }
    int run = (t > 0) ? sh[t - 1] : 0;
    for (int j = 0; j < CH; j++) {
        int idx = base + j;
        if (idx <= N_) {
            g_rowptr[idx] = run;
            if (idx < N_) run += g_deg[idx];
        }
    }
}

__global__ void scatter_kernel(const int* __restrict__ ei) {
    int e = blockIdx.x * blockDim.x + threadIdx.x;
    if (e >= E2_) return;
    int s, d;
    if (e < E_) { s = ei[e]; d = ei[E_ + e]; }
    else        { s = e - E_; d = s; }
    int pos = g_rowptr[d] + atomicAdd(&g_cursor[d], 1);
    g_srcs[pos] = s;
}

// -------------------- GEMM: C[M,128] = preop(A)[M,128] @ W[128,128] + bias -----
// PRE: 0 = identity, 1 = LayerNorm(graph)+ReLU fused on A, 2 = A + resid
template<int PRE>
__global__ __launch_bounds__(256) void gemm_kernel(
    const float* __restrict__ A, const float* __restrict__ W,
    const float* __restrict__ bias, float* __restrict__ C,
    const float* __restrict__ lnG, const float* __restrict__ lnB,
    int lnslot, const float* __restrict__ resid)
{
    __shared__ __align__(16) float As[16][68];
    __shared__ __align__(16) float Bs[16][128];
    const int tid  = threadIdx.x;
    const int row0 = blockIdx.x * 64;

    float mu = 0.f, inv = 0.f;
    if (PRE == 1) {
        double s  = g_lnred[lnslot * 2 + 0];
        double sq = g_lnred[lnslot * 2 + 1];
        const double cnt = (double)N_ * (double)D_;
        double m   = s / cnt;
        double var = sq / cnt - m * m;
        mu  = (float)m;
        inv = (float)(1.0 / sqrt(var + (double)EPS_));
    }

    const int ar = tid >> 2;            // A row within tile 0..63
    const int ak = (tid & 3) * 4;       // A k offset 0,4,8,12
    const int bk = tid >> 5;            // B k row 0..7
    const int bn = (tid & 31) * 4;      // B col
    const int ty = tid >> 5;            // 0..7 (== warp id)
    const int tx = tid & 31;

    float acc[8][4];
#pragma unroll
    for (int r = 0; r < 8; r++)
#pragma unroll
        for (int c = 0; c < 4; c++) acc[r][c] = 0.f;

    const int grow = row0 + ar;
    const bool arow_ok = grow < N_;

    for (int k0 = 0; k0 < 128; k0 += 16) {
        float4 av = make_float4(0.f, 0.f, 0.f, 0.f);
        if (arow_ok) av = *(const float4*)(A + (size_t)grow * D_ + k0 + ak);
        if (PRE == 1) {
            float* p = &av.x;
#pragma unroll
            for (int j = 0; j < 4; j++) {
                int k = k0 + ak + j;
                float v = (p[j] - mu) * inv * lnG[k] + lnB[k];
                p[j] = fmaxf(v, 0.f);
            }
        } else if (PRE == 2) {
            if (arow_ok) {
                float4 rv = *(const float4*)(resid + (size_t)grow * D_ + k0 + ak);
                av.x += rv.x; av.y += rv.y; av.z += rv.z; av.w += rv.w;
            }
        }
        As[ak + 0][ar] = av.x;
        As[ak + 1][ar] = av.y;
        As[ak + 2][ar] = av.z;
        As[ak + 3][ar] = av.w;

        *(float4*)&Bs[bk][bn]     = *(const float4*)(W + (size_t)(k0 + bk) * D_ + bn);
        *(float4*)&Bs[bk + 8][bn] = *(const float4*)(W + (size_t)(k0 + bk + 8) * D_ + bn);
        __syncthreads();

#pragma unroll
        for (int k = 0; k < 16; k++) {
            float4 b  = *(float4*)&Bs[k][tx * 4];
            float4 a0 = *(float4*)&As[k][ty * 8];
            float4 a1 = *(float4*)&As[k][ty * 8 + 4];
            float a[8] = {a0.x, a0.y, a0.z, a0.w, a1.x, a1.y, a1.z, a1.w};
#pragma unroll
            for (int r = 0; r < 8; r++) {
                acc[r][0] += a[r] * b.x;
                acc[r][1] += a[r] * b.y;
                acc[r][2] += a[r] * b.z;
                acc[r][3] += a[r] * b.w;
            }
        }
        __syncthreads();
    }

    float4 bv = *(const float4*)(bias + tx * 4);
#pragma unroll
    for (int r = 0; r < 8; r++) {
        int gr = row0 + ty * 8 + r;
        if (gr < N_) {
            float4 o = make_float4(acc[r][0] + bv.x, acc[r][1] + bv.y,
                                   acc[r][2] + bv.z, acc[r][3] + bv.w);
            *(float4*)(C + (size_t)gr * D_ + tx * 4) = o;
        }
    }
}

// -------------------- per-node online-softmax aggregation (warp per dst) ----
__global__ __launch_bounds__(256) void agg_kernel(
    const float* __restrict__ att, const float* __restrict__ cbias)
{
    int warp = (blockIdx.x * blockDim.x + threadIdx.x) >> 5;
    int lane = threadIdx.x & 31;
    if (warp >= N_) return;

    const float4 attv = ((const float4*)att)[lane];
    const float4 xrv  = ((const float4*)(g_xr + (size_t)warp * D_))[lane];

    int beg = g_rowptr[warp], end = g_rowptr[warp + 1];

    float m = -INFINITY, lsum = 0.f;
    float4 acc = make_float4(0.f, 0.f, 0.f, 0.f);

    for (int e = beg; e < end; e++) {
        int s = g_srcs[e];
        float4 v = ((const float4*)(g_xl + (size_t)s * D_))[lane];
        float p = leaky(v.x + xrv.x) * attv.x
                + leaky(v.y + xrv.y) * attv.y
                + leaky(v.z + xrv.z) * attv.z
                + leaky(v.w + xrv.w) * attv.w;
#pragma unroll
        for (int o = 16; o > 0; o >>= 1)
            p += __shfl_xor_sync(0xffffffffu, p, o);

        float mn    = fmaxf(m, p);
        float scale = __expf(m - mn);
        float w     = __expf(p - mn);
        acc.x = acc.x * scale + w * v.x;
        acc.y = acc.y * scale + w * v.y;
        acc.z = acc.z * scale + w * v.z;
        acc.w = acc.w * scale + w * v.w;
        lsum  = lsum * scale + w;
        m = mn;
    }

    float invl = 1.f / lsum;
    float4 cb = ((const float4*)cbias)[lane];
    float4 o = make_float4(acc.x * invl + cb.x, acc.y * invl + cb.y,
                           acc.z * invl + cb.z, acc.w * invl + cb.w);
    ((float4*)(g_xg + (size_t)warp * D_))[lane] = o;
}

// -------------------- global LN stats (sum, sumsq over all N*D) -------------
__global__ void lnstats_kernel(int slot) {
    __shared__ float ss[256], sq[256];
    int tid = threadIdx.x;
    int stride = gridDim.x * blockDim.x;
    float s = 0.f, q = 0.f;
    for (int i = blockIdx.x * blockDim.x + tid; i < N_ * 32; i += stride) {
        float4 v = ((const float4*)g_xg)[i];
        s += v.x + v.y + v.z + v.w;
        q += v.x * v.x + v.y * v.y + v.z * v.z + v.w * v.w;
    }
    ss[tid] = s; sq[tid] = q;
    __syncthreads();
    for (int o = 128; o > 0; o >>= 1) {
        if (tid < o) { ss[tid] += ss[tid + o]; sq[tid] += sq[tid + o]; }
        __syncthreads();
    }
    if (tid == 0) {
        atomicAdd(&g_lnred[slot * 2 + 0], (double)ss[0]);
        atomicAdd(&g_lnred[slot * 2 + 1], (double)sq[0]);
    }
}

// -------------------- BatchNorm stats + normalize (on d_out) ----------------
__global__ void bnstats_kernel(const float* __restrict__ out) {
    int c = threadIdx.x;   // 128 threads
    float s = 0.f, q = 0.f;
    for (int r = blockIdx.x; r < N_; r += gridDim.x) {
        float v = out[(size_t)r * D_ + c];
        s += v; q += v * v;
    }
    atomicAdd(&g_bnsum[c], s);
    atomicAdd(&g_bnsq[c], q);
}

__global__ void bnnorm_kernel(float* __restrict__ out,
                              const float* __restrict__ bng,
                              const float* __restrict__ bnb) {
    int i = blockIdx.x * blockDim.x + threadIdx.x;   // over N_*32 float4s
    if (i >= N_ * 32) return;
    int c4 = i & 31;
    float4 v  = ((float4*)out)[i];
    float4 su = ((const float4*)g_bnsum)[c4];
    float4 qu = ((const float4*)g_bnsq)[c4];
    float4 g  = ((const float4*)bng)[c4];
    float4 b  = ((const float4*)bnb)[c4];
    const float invN = 1.f / (float)N_;

    float mu, var;
    mu = su.x * invN; var = qu.x * invN - mu * mu;
    v.x = (v.x - mu) * rsqrtf(var + EPS_) * g.x + b.x;
    mu = su.y * invN; var = qu.y * invN - mu * mu;
    v.y = (v.y - mu) * rsqrtf(var + EPS_) * g.y + b.y;
    mu = su.z * invN; var = qu.z * invN - mu * mu;
    v.z = (v.z - mu) * rsqrtf(var + EPS_) * g.z + b.z;
    mu = su.w * invN; var = qu.w * invN - mu * mu;
    v.w = (v.w - mu) * rsqrtf(var + EPS_) * g.w + b.w;
    ((float4*)out)[i] = v;
}

// -------------------- launch --------------------
extern "C" void kernel_launch(void* const* d_in, const int* in_sizes, int n_in,
                              void* d_out, int out_size) {
    const int*   x    = (const int*)d_in[0];
    const int*   ei   = (const int*)d_in[1];
    const float* emb  = (const float*)d_in[2];
    const float* Wl   = (const float*)d_in[3];
    const float* bl   = (const float*)d_in[4];
    const float* Wr   = (const float*)d_in[5];
    const float* br   = (const float*)d_in[6];
    const float* att  = (const float*)d_in[7];
    const float* cb   = (const float*)d_in[8];
    const float* lng  = (const float*)d_in[9];
    const float* lnb  = (const float*)d_in[10];
    const float* linW = (const float*)d_in[11];
    const float* linb = (const float*)d_in[12];
    const float* bng  = (const float*)d_in[13];
    const float* bnb  = (const float*)d_in[14];
    float* out = (float*)d_out;

    float *p_h, *p_xg, *p_xl, *p_xr;
    cudaGetSymbolAddress((void**)&p_h,  g_h);
    cudaGetSymbolAddress((void**)&p_xg, g_xg);
    cudaGetSymbolAddress((void**)&p_xl, g_xl);
    cudaGetSymbolAddress((void**)&p_xr, g_xr);

    const int TPB = 256;
    zero_kernel<<<(N_ + TPB - 1) / TPB, TPB>>>();
    gather_kernel<<<(N_ * 32 + TPB - 1) / TPB, TPB>>>(x, emb);
    hist_kernel<<<(E2_ + TPB - 1) / TPB, TPB>>>(ei);
    scan_kernel<<<1, 1024>>>();
    scatter_kernel<<<(E2_ + TPB - 1) / TPB, TPB>>>(ei);

    const int GEMM_GRID = (N_ + 63) / 64;   // 469
    const int AGG_GRID  = (N_ * 32 + TPB - 1) / TPB;  // warp per node

    for (int i = 0; i < L_; i++) {
        const float* Ain = (i == 0) ? p_h : p_xg;
        if (i == 0) {
            gemm_kernel<0><<<GEMM_GRID, 256>>>(Ain, Wl + i * D_ * D_, bl + i * D_,
                                               p_xl, nullptr, nullptr, 0, nullptr);
            gemm_kernel<0><<<GEMM_GRID, 256>>>(Ain, Wr + i * D_ * D_, br + i * D_,
                                               p_xr, nullptr, nullptr, 0, nullptr);
        } else {
            gemm_kernel<1><<<GEMM_GRID, 256>>>(Ain, Wl + i * D_ * D_, bl + i * D_,
                                               p_xl, lng + (i - 1) * D_,
                                               lnb + (i - 1) * D_, i - 1, nullptr);
            gemm_kernel<1><<<GEMM_GRID, 256>>>(Ain, Wr + i * D_ * D_, br + i * D_,
                                               p_xr, lng + (i - 1) * D_,
                                               lnb + (i - 1) * D_, i - 1, nullptr);
        }
        agg_kernel<<<AGG_GRID, 256>>>(att + i * D_, cb + i * D_);
        if (i < L_ - 1) {
            lnstats_kernel<<<1024, 256>>>(i);
        }
    }

    // final: out = (h + xg) @ lin_W + lin_b, then BatchNorm1d (train-mode stats)
    gemm_kernel<2><<<GEMM_GRID, 256>>>(p_xg, linW, linb, out,
                                       nullptr, nullptr, 0, p_h);
    bnstats_kernel<<<256, D_>>>(out);
    bnnorm_kernel<<<(N_ * 32 + TPB - 1) / TPB, TPB>>>(out, bng, bnb);
}

// round 5
// speedup vs baseline: 1.2066x; 1.2066x over previous
#include <cuda_runtime.h>
#include <cuda_bf16.h>
#include <math.h>
#include <stdint.h>

// Problem constants
#define N_ 30000
#define D_ 128
#define E_ 240000
#define E2_ (E_ + N_)          // 270000
#define L_ 6
#define NEG_SLOPE 0.2f
#define EPS_ 1e-5f

// -------------------- device scratch --------------------
__device__ float g_h[N_ * D_];
__device__ float g_xg[N_ * D_];
__device__ float g_xl[N_ * D_];
__device__ float g_xr[N_ * D_];
__device__ float g_Whi[13 * D_ * D_];  // W^T, tf32 hi part
__device__ float g_Wlo[13 * D_ * D_];  // W^T, tf32 lo residual

__device__ int    g_deg[N_];
__device__ int    g_cursor[N_];
__device__ int    g_rowptr[N_ + 1];
__device__ int    g_srcs[E2_];
__device__ int    g_scanbuf[30720];
__device__ int    g_bsum[32];

__device__ double g_lnred[12];
__device__ float  g_bnsum[D_];
__device__ float  g_bnsq[D_];

// -------------------- helpers --------------------
__device__ __forceinline__ uint32_t tf32r(float f) {
    uint32_t r;
    asm("cvt.rna.tf32.f32 %0, %1;" : "=r"(r) : "f"(f));
    return r;
}
__device__ __forceinline__ void mma_tf32(float* d, const uint32_t* a, const uint32_t* b) {
    asm volatile(
        "mma.sync.aligned.m16n8k8.row.col.f32.tf32.tf32.f32 "
        "{%0,%1,%2,%3}, {%4,%5,%6,%7}, {%8,%9}, {%0,%1,%2,%3};"
        : "+f"(d[0]), "+f"(d[1]), "+f"(d[2]), "+f"(d[3])
        : "r"(a[0]), "r"(a[1]), "r"(a[2]), "r"(a[3]), "r"(b[0]), "r"(b[1]));
}
__device__ __forceinline__ float leaky(float v) { return v > 0.f ? v : NEG_SLOPE * v; }

// -------------------- small kernels --------------------
__global__ void zero_kernel() {
    int i = blockIdx.x * blockDim.x + threadIdx.x;
    if (i < N_) { g_deg[i] = 0; g_cursor[i] = 0; }
    if (i < 12) g_lnred[i] = 0.0;
    if (i < D_) { g_bnsum[i] = 0.f; g_bnsq[i] = 0.f; }
}

__global__ void gather_kernel(const int* __restrict__ x, const float* __restrict__ emb) {
    int i = blockIdx.x * blockDim.x + threadIdx.x;
    if (i >= N_ * 32) return;
    int n = i >> 5, c4 = i & 31;
    ((float4*)g_h)[i] = ((const float4*)(emb + (size_t)x[n] * D_))[c4];
}

__global__ void hist_kernel(const int* __restrict__ ei) {
    int e = blockIdx.x * blockDim.x + threadIdx.x;
    if (e >= E2_) return;
    int d = (e < E_) ? ei[E_ + e] : (e - E_);
    atomicAdd(&g_deg[d], 1);
}

// coalesced 3-phase scan
__global__ void scan1_kernel() {
    __shared__ int sh[1024];
    int t = threadIdx.x, i = blockIdx.x * 1024 + t;
    int v = (i < N_) ? g_deg[i] : 0;
    sh[t] = v;
    __syncthreads();
    for (int o = 1; o < 1024; o <<= 1) {
        int u = (t >= o) ? sh[t - o] : 0;
        __syncthreads();
        sh[t] += u;
        __syncthreads();
    }
    g_scanbuf[i] = sh[t];
    if (t == 1023) g_bsum[blockIdx.x] = sh[1023];
}
__global__ void scan2_kernel() {
    int t = threadIdx.x;
    int orig = (t < 30) ? g_bsum[t] : 0;
    int v = orig;
    for (int o = 1; o < 32; o <<= 1) {
        int u = __shfl_up_sync(0xffffffffu, v, o);
        if (t >= o) v += u;
    }
    if (t < 30) g_bsum[t] = v - orig;   // exclusive block offsets
}
__global__ void scan3_kernel() {
    int t = threadIdx.x, i = blockIdx.x * 1024 + t;
    if (i > N_) return;
    int v = (i < N_) ? g_deg[i] : 0;
    g_rowptr[i] = g_bsum[blockIdx.x] + g_scanbuf[i] - v;
}

__global__ void scatter_kernel(const int* __restrict__ ei) {
    int e = blockIdx.x * blockDim.x + threadIdx.x;
    if (e >= E2_) return;
    int s, d;
    if (e < E_) { s = ei[e]; d = ei[E_ + e]; }
    else        { s = e - E_; d = s; }
    int pos = g_rowptr[d] + atomicAdd(&g_cursor[d], 1);
    g_srcs[pos] = s;
}

// transpose + tf32 hi/lo split of the 13 weight matrices: Wt[n][k] = W[k][n]
__global__ void tr_kernel(const float* __restrict__ Wl, const float* __restrict__ Wr,
                          const float* __restrict__ linW) {
    __shared__ float t[32][33];
    int mat = blockIdx.z;
    const float* src = (mat < 6) ? (Wl + mat * 16384)
                     : (mat < 12) ? (Wr + (mat - 6) * 16384) : linW;
    int bx = blockIdx.x * 32, by = blockIdx.y * 32;
    for (int i = threadIdx.y; i < 32; i += 8)
        t[i][threadIdx.x] = src[(by + i) * D_ + bx + threadIdx.x];
    __syncthreads();
    for (int i = threadIdx.y; i < 32; i += 8) {
        float v = t[threadIdx.x][i];
        float hi = __uint_as_float(tf32r(v));
        float lo = __uint_as_float(tf32r(v - hi));
        size_t o = (size_t)mat * 16384 + (size_t)(bx + i) * D_ + by + threadIdx.x;
        g_Whi[o] = hi;
        g_Wlo[o] = lo;
    }
}

// -------------------- 3xTF32 mma.sync GEMM --------------------
// C = preop(A)[128-row tile] @ W   (W^T hi/lo given as [N,K] row-major)
// PRE: 0 identity, 1 LN(graph)+ReLU, 2 A+resid.   NB: 1 or 2 weight matrices.
// K processed in two halves of 64 so 6 half-tiles fit SMEM.
#define PITCH 68
#define HTILE (128 * PITCH)                 // floats per half-tile
#define SMEM_NB1 (4 * HTILE * 4)            // bytes
#define SMEM_NB2 (6 * HTILE * 4)

template<int PRE, int NB>
__global__ __launch_bounds__(256, 1) void gat_gemm(
    const float* __restrict__ A, const float* __restrict__ resid,
    const float* __restrict__ WhA, const float* __restrict__ WlA,
    const float* __restrict__ WhB, const float* __restrict__ WlB,
    const float* __restrict__ biasA, const float* __restrict__ biasB,
    float* __restrict__ CA, float* __restrict__ CB,
    const float* __restrict__ lnG, const float* __restrict__ lnB, int lnslot)
{
    extern __shared__ float sm[];
    float* Ah  = sm;
    float* Al  = sm + HTILE;
    float* B0h = sm + 2 * HTILE;
    float* B0l = sm + 3 * HTILE;
    float* B1h = sm + 4 * HTILE;
    float* B1l = sm + 5 * HTILE;

    const int tid = threadIdx.x, wid = tid >> 5, lane = tid & 31;
    const int row0 = blockIdx.x * 128;

    float mu = 0.f, inv = 0.f;
    if (PRE == 1) {
        double s  = g_lnred[lnslot * 2 + 0];
        double sq = g_lnred[lnslot * 2 + 1];
        const double cnt = (double)N_ * (double)D_;
        double m = s / cnt;
        mu  = (float)m;
        inv = (float)(1.0 / sqrt(sq / cnt - m * m + (double)EPS_));
    }

    const int g  = lane >> 2;        // groupID
    const int tg = lane & 3;         // thread-in-group
    const int wr = (wid >> 2) * 64;  // warp row offset (0/64)
    const int wc = (wid & 3) * 32;   // warp col offset

    float acc0[4][4][4], acc1[4][4][4];
#pragma unroll
    for (int mi = 0; mi < 4; mi++)
#pragma unroll
        for (int ni = 0; ni < 4; ni++)
#pragma unroll
            for (int j = 0; j < 4; j++) {
                acc0[mi][ni][j] = 0.f;
                if (NB == 2) acc1[mi][ni][j] = 0.f;
            }

    for (int kh = 0; kh < 2; kh++) {
        if (kh) __syncthreads();   // smem reuse: wait for previous compute

        // ---- stage A half-tile (pre-op + hi/lo split) ----
#pragma unroll 2
        for (int i = 0; i < 8; i++) {
            int idx = i * 256 + tid;
            int r = idx >> 4, c4 = idx & 15;
            int k = kh * 64 + c4 * 4;
            int gr = row0 + r;
            float4 v = make_float4(0.f, 0.f, 0.f, 0.f);
            if (gr < N_) v = *(const float4*)(A + (size_t)gr * D_ + k);
            if (PRE == 1) {
                float4 lg = *(const float4*)(lnG + k);
                float4 lb = *(const float4*)(lnB + k);
                v.x = fmaxf((v.x - mu) * inv * lg.x + lb.x, 0.f);
                v.y = fmaxf((v.y - mu) * inv * lg.y + lb.y, 0.f);
                v.z = fmaxf((v.z - mu) * inv * lg.z + lb.z, 0.f);
                v.w = fmaxf((v.w - mu) * inv * lg.w + lb.w, 0.f);
            } else if (PRE == 2) {
                if (gr < N_) {
                    float4 rv = *(const float4*)(resid + (size_t)gr * D_ + k);
                    v.x += rv.x; v.y += rv.y; v.z += rv.z; v.w += rv.w;
                }
            }
            float4 h, l;
            h.x = __uint_as_float(tf32r(v.x)); l.x = __uint_as_float(tf32r(v.x - h.x));
            h.y = __uint_as_float(tf32r(v.y)); l.y = __uint_as_float(tf32r(v.y - h.y));
            h.z = __uint_as_float(tf32r(v.z)); l.z = __uint_as_float(tf32r(v.z - h.z));
            h.w = __uint_as_float(tf32r(v.w)); l.w = __uint_as_float(tf32r(v.w - h.w));
            *(float4*)&Ah[r * PITCH + c4 * 4] = h;
            *(float4*)&Al[r * PITCH + c4 * 4] = l;
        }
        // ---- stage B half-tiles (pre-split in global) ----
#pragma unroll 2
        for (int i = 0; i < 8; i++) {
            int idx = i * 256 + tid;
            int r = idx >> 4, c4 = idx & 15;
            int k = kh * 64 + c4 * 4;
            int so = r * PITCH + c4 * 4;
            size_t go = (size_t)r * D_ + k;
            *(float4*)&B0h[so] = *(const float4*)(WhA + go);
            *(float4*)&B0l[so] = *(const float4*)(WlA + go);
            if (NB == 2) {
                *(float4*)&B1h[so] = *(const float4*)(WhB + go);
                *(float4*)&B1l[so] = *(const float4*)(WlB + go);
            }
        }
        __syncthreads();

        // ---- compute 8 k-steps on this half ----
#pragma unroll 2
        for (int ks = 0; ks < 8; ks++) {
            int k0 = ks * 8;
            uint32_t ah[4][4], al[4][4];
#pragma unroll
            for (int mi = 0; mi < 4; mi++) {
                int rb = wr + mi * 16;
                int o1 = (rb + g) * PITCH + k0 + tg;
                int o2 = (rb + g + 8) * PITCH + k0 + tg;
                ah[mi][0] = __float_as_uint(Ah[o1]);
                ah[mi][1] = __float_as_uint(Ah[o2]);
                ah[mi][2] = __float_as_uint(Ah[o1 + 4]);
                ah[mi][3] = __float_as_uint(Ah[o2 + 4]);
                al[mi][0] = __float_as_uint(Al[o1]);
                al[mi][1] = __float_as_uint(Al[o2]);
                al[mi][2] = __float_as_uint(Al[o1 + 4]);
                al[mi][3] = __float_as_uint(Al[o2 + 4]);
            }
            {
                uint32_t bh[4][2], bl[4][2];
#pragma unroll
                for (int ni = 0; ni < 4; ni++) {
                    int o = (wc + ni * 8 + g) * PITCH + k0 + tg;
                    bh[ni][0] = __float_as_uint(B0h[o]);
                    bh[ni][1] = __float_as_uint(B0h[o + 4]);
                    bl[ni][0] = __float_as_uint(B0l[o]);
                    bl[ni][1] = __float_as_uint(B0l[o + 4]);
                }
#pragma unroll
                for (int mi = 0; mi < 4; mi++)
#pragma unroll
                    for (int ni = 0; ni < 4; ni++) {
                        mma_tf32(acc0[mi][ni], ah[mi], bh[ni]);
                        mma_tf32(acc0[mi][ni], ah[mi], bl[ni]);
                        mma_tf32(acc0[mi][ni], al[mi], bh[ni]);
                    }
            }
            if (NB == 2) {
                uint32_t bh[4][2], bl[4][2];
#pragma unroll
                for (int ni = 0; ni < 4; ni++) {
                    int o = (wc + ni * 8 + g) * PITCH + k0 + tg;
                    bh[ni][0] = __float_as_uint(B1h[o]);
                    bh[ni][1] = __float_as_uint(B1h[o + 4]);
                    bl[ni][0] = __float_as_uint(B1l[o]);
                    bl[ni][1] = __float_as_uint(B1l[o + 4]);
                }
#pragma unroll
                for (int mi = 0; mi < 4; mi++)
#pragma unroll
                    for (int ni = 0; ni < 4; ni++) {
                        mma_tf32(acc1[mi][ni], ah[mi], bh[ni]);
                        mma_tf32(acc1[mi][ni], ah[mi], bl[ni]);
                        mma_tf32(acc1[mi][ni], al[mi], bh[ni]);
                    }
            }
        }
    }

    // ---- epilogue ----
#pragma unroll
    for (int mat = 0; mat < NB; mat++) {
        const float* bias = mat ? biasB : biasA;
        float* C          = mat ? CB : CA;
#pragma unroll
        for (int mi = 0; mi < 4; mi++) {
            int r1 = row0 + wr + mi * 16 + g;
            int r2 = r1 + 8;
#pragma unroll
            for (int ni = 0; ni < 4; ni++) {
                float* a = mat ? acc1[mi][ni] : acc0[mi][ni];
                int col = wc + ni * 8 + tg * 2;
                float2 bv = *(const float2*)(bias + col);
                if (r1 < N_) {
                    float2 o = make_float2(a[0] + bv.x, a[1] + bv.y);
                    *(float2*)(C + (size_t)r1 * D_ + col) = o;
                }
                if (r2 < N_) {
                    float2 o = make_float2(a[2] + bv.x, a[3] + bv.y);
                    *(float2*)(C + (size_t)r2 * D_ + col) = o;
                }
            }
        }
    }
}

// -------------------- aggregation (warp per dst) + fused LN stats ----------
template<int STATS>
__global__ __launch_bounds__(256) void agg_kernel(
    const float* __restrict__ att, const float* __restrict__ cbias, int slot)
{
    __shared__ float ssum[8], ssq[8];
    int tid = threadIdx.x;
    int warp = (blockIdx.x * blockDim.x + tid) >> 5;
    int lane = tid & 31;
    int wid = tid >> 5;

    float4 o = make_float4(0.f, 0.f, 0.f, 0.f);
    if (warp < N_) {
        const float4 attv = ((const float4*)att)[lane];
        const float4 xrv  = ((const float4*)(g_xr + (size_t)warp * D_))[lane];
        int beg = g_rowptr[warp], end = g_rowptr[warp + 1];

        float m = -INFINITY, lsum = 0.f;
        float4 acc = make_float4(0.f, 0.f, 0.f, 0.f);
        for (int e = beg; e < end; e++) {
            int s = g_srcs[e];
            float4 v = ((const float4*)(g_xl + (size_t)s * D_))[lane];
            float p = leaky(v.x + xrv.x) * attv.x
                    + leaky(v.y + xrv.y) * attv.y
                    + leaky(v.z + xrv.z) * attv.z
                    + leaky(v.w + xrv.w) * attv.w;
#pragma unroll
            for (int of = 16; of > 0; of >>= 1)
                p += __shfl_xor_sync(0xffffffffu, p, of);
            float mn    = fmaxf(m, p);
            float scale = __expf(m - mn);
            float w     = __expf(p - mn);
            acc.x = acc.x * scale + w * v.x;
            acc.y = acc.y * scale + w * v.y;
            acc.z = acc.z * scale + w * v.z;
            acc.w = acc.w * scale + w * v.w;
            lsum  = lsum * scale + w;
            m = mn;
        }
        float invl = 1.f / lsum;
        float4 cb = ((const float4*)cbias)[lane];
        o = make_float4(acc.x * invl + cb.x, acc.y * invl + cb.y,
                        acc.z * invl + cb.z, acc.w * invl + cb.w);
        ((float4*)(g_xg + (size_t)warp * D_))[lane] = o;
    }

    if (STATS) {
        float s = o.x + o.y + o.z + o.w;
        float q = o.x * o.x + o.y * o.y + o.z * o.z + o.w * o.w;
#pragma unroll
        for (int of = 16; of > 0; of >>= 1) {
            s += __shfl_xor_sync(0xffffffffu, s, of);
            q += __shfl_xor_sync(0xffffffffu, q, of);
        }
        if (lane == 0) { ssum[wid] = s; ssq[wid] = q; }
        __syncthreads();
        if (tid == 0) {
            double S = 0.0, Q = 0.0;
#pragma unroll
            for (int i = 0; i < 8; i++) { S += (double)ssum[i]; Q += (double)ssq[i]; }
            atomicAdd(&g_lnred[slot * 2 + 0], S);
            atomicAdd(&g_lnred[slot * 2 + 1], Q);
        }
    }
}

// -------------------- BatchNorm --------------------
__global__ void bnstats_kernel(const float* __restrict__ out) {
    int c = threadIdx.x;
    float s = 0.f, q = 0.f;
    for (int r = blockIdx.x; r < N_; r += gridDim.x) {
        float v = out[(size_t)r * D_ + c];
        s += v; q += v * v;
    }
    atomicAdd(&g_bnsum[c], s);
    atomicAdd(&g_bnsq[c], q);
}

__global__ void bnnorm_kernel(float* __restrict__ out,
                              const float* __restrict__ bng,
                              const float* __restrict__ bnb) {
    int i = blockIdx.x * blockDim.x + threadIdx.x;
    if (i >= N_ * 32) return;
    int c4 = i & 31;
    float4 v  = ((float4*)out)[i];
    float4 su = ((const float4*)g_bnsum)[c4];
    float4 qu = ((const float4*)g_bnsq)[c4];
    float4 g  = ((const float4*)bng)[c4];
    float4 b  = ((const float4*)bnb)[c4];
    const float invN = 1.f / (float)N_;
    float mu, var;
    mu = su.x * invN; var = qu.x * invN - mu * mu;
    v.x = (v.x - mu) * rsqrtf(var + EPS_) * g.x + b.x;
    mu = su.y * invN; var = qu.y * invN - mu * mu;
    v.y = (v.y - mu) * rsqrtf(var + EPS_) * g.y + b.y;
    mu = su.z * invN; var = qu.z * invN - mu * mu;
    v.z = (v.z - mu) * rsqrtf(var + EPS_) * g.z + b.z;
    mu = su.w * invN; var = qu.w * invN - mu * mu;
    v.w = (v.w - mu) * rsqrtf(var + EPS_) * g.w + b.w;
    ((float4*)out)[i] = v;
}

// -------------------- launch --------------------
extern "C" void kernel_launch(void* const* d_in, const int* in_sizes, int n_in,
                              void* d_out, int out_size) {
    const int*   x    = (const int*)d_in[0];
    const int*   ei   = (const int*)d_in[1];
    const float* emb  = (const float*)d_in[2];
    const float* Wl   = (const float*)d_in[3];
    const float* bl   = (const float*)d_in[4];
    const float* Wr   = (const float*)d_in[5];
    const float* br   = (const float*)d_in[6];
    const float* att  = (const float*)d_in[7];
    const float* cb   = (const float*)d_in[8];
    const float* lng  = (const float*)d_in[9];
    const float* lnb  = (const float*)d_in[10];
    const float* linW = (const float*)d_in[11];
    const float* linb = (const float*)d_in[12];
    const float* bng  = (const float*)d_in[13];
    const float* bnb  = (const float*)d_in[14];
    float* out = (float*)d_out;

    float *p_h, *p_xg, *p_xl, *p_xr, *p_Whi, *p_Wlo;
    cudaGetSymbolAddress((void**)&p_h,  g_h);
    cudaGetSymbolAddress((void**)&p_xg, g_xg);
    cudaGetSymbolAddress((void**)&p_xl, g_xl);
    cudaGetSymbolAddress((void**)&p_xr, g_xr);
    cudaGetSymbolAddress((void**)&p_Whi, g_Whi);
    cudaGetSymbolAddress((void**)&p_Wlo, g_Wlo);

    cudaFuncSetAttribute(gat_gemm<0,2>, cudaFuncAttributeMaxDynamicSharedMemorySize, SMEM_NB2);
    cudaFuncSetAttribute(gat_gemm<1,2>, cudaFuncAttributeMaxDynamicSharedMemorySize, SMEM_NB2);
    cudaFuncSetAttribute(gat_gemm<2,1>, cudaFuncAttributeMaxDynamicSharedMemorySize, SMEM_NB1);

    const int TPB = 256;
    zero_kernel<<<(N_ + TPB - 1) / TPB, TPB>>>();
    gather_kernel<<<(N_ * 32 + TPB - 1) / TPB, TPB>>>(x, emb);
    hist_kernel<<<(E2_ + TPB - 1) / TPB, TPB>>>(ei);
    scan1_kernel<<<30, 1024>>>();
    scan2_kernel<<<1, 32>>>();
    scan3_kernel<<<30, 1024>>>();
    scatter_kernel<<<(E2_ + TPB - 1) / TPB, TPB>>>(ei);
    tr_kernel<<<dim3(4, 4, 13), dim3(32, 8)>>>(Wl, Wr, linW);

    const int GEMM_GRID = (N_ + 127) / 128;          // 235
    const int AGG_GRID  = (N_ * 32 + TPB - 1) / TPB; // 3750

    for (int i = 0; i < L_; i++) {
        const float* Ain = (i == 0) ? p_h : p_xg;
        const float* WhL = p_Whi + (size_t)i * 16384;
        const float* WlL = p_Wlo + (size_t)i * 16384;
        const float* WhR = p_Whi + (size_t)(6 + i) * 16384;
        const float* WlR = p_Wlo + (size_t)(6 + i) * 16384;
        if (i == 0) {
            gat_gemm<0,2><<<GEMM_GRID, 256, SMEM_NB2>>>(
                Ain, nullptr, WhL, WlL, WhR, WlR, bl + i * D_, br + i * D_,
                p_xl, p_xr, nullptr, nullptr, 0);
        } else {
            gat_gemm<1,2><<<GEMM_GRID, 256, SMEM_NB2>>>(
                Ain, nullptr, WhL, WlL, WhR, WlR, bl + i * D_, br + i * D_,
                p_xl, p_xr, lng + (i - 1) * D_, lnb + (i - 1) * D_, i - 1);
        }
        if (i < L_ - 1)
            agg_kernel<1><<<AGG_GRID, 256>>>(att + i * D_, cb + i * D_, i);
        else
            agg_kernel<0><<<AGG_GRID, 256>>>(att + i * D_, cb + i * D_, 0);
    }

    gat_gemm<2,1><<<GEMM_GRID, 256, SMEM_NB1>>>(
        p_xg, p_h, p_Whi + (size_t)12 * 16384, p_Wlo + (size_t)12 * 16384,
        nullptr, nullptr, linb, nullptr,
        out, nullptr, nullptr, nullptr, 0);
    bnstats_kernel<<<256, D_>>>(out);
    bnnorm_kernel<<<(N_ * 32 + TPB - 1) / TPB, TPB>>>(out, bng, bnb);
}